// round 11
// baseline (speedup 1.0000x reference)
#include <cuda_runtime.h>
#include <cuda_bf16.h>
#include <mma.h>
#include <math.h>

using namespace nvcuda;

// Problem constants
#define BATCH   4
#define HH      64
#define WW      64
#define CIN     128
#define FILTERS 128
#define HEADS   8
#define HSIZE   16
#define K0      7
#define K1      7
#define KD      49
#define NPIX    (BATCH*HH*WW)      // 16384
#define NQKV    384                 // q|k|v concat

typedef unsigned long long ull;
typedef unsigned int u32;

// packed f32x2 helpers (sm_100+)
#define FMA2(d, a, b)   asm("fma.rn.f32x2 %0, %1, %2, %0;" : "+l"(d) : "l"(a), "l"(b))
#define MUL2(d, a, b)   asm("mul.rn.f32x2 %0, %1, %2;"     : "=l"(d) : "l"(a), "l"(b))
#define ADD2(d, a, b)   asm("add.rn.f32x2 %0, %1, %2;"     : "=l"(d) : "l"(a), "l"(b))
#define PACK2(d, x, y)  asm("mov.b64 %0, {%1, %2};" : "=l"(d) : "f"(x), "f"(y))
#define UNPK2(lo, hi, s) asm("mov.b64 {%0, %1}, %2;" : "=f"(lo), "=f"(hi) : "l"(s))

__device__ float g_QKV[NPIX * NQKV];

// pre-split bf16 hi/lo storage (4 bf16 per ull)
#define XCHUNKS (NPIX * CIN / 4)          // 524288
#define WCHUNKS (3 * CIN * FILTERS / 4)   // 12288
__device__ ull g_Xhi[XCHUNKS];
__device__ ull g_Xlo[XCHUNKS];
__device__ ull g_Whi[WCHUNKS];
__device__ ull g_Wlo[WCHUNKS];

__device__ __forceinline__ void split4(float4 v, ull& hi, ull& lo) {
    __nv_bfloat16 h0 = __float2bfloat16_rn(v.x);
    __nv_bfloat16 h1 = __float2bfloat16_rn(v.y);
    __nv_bfloat16 h2 = __float2bfloat16_rn(v.z);
    __nv_bfloat16 h3 = __float2bfloat16_rn(v.w);
    __nv_bfloat16 l0 = __float2bfloat16_rn(v.x - __bfloat162float(h0));
    __nv_bfloat16 l1 = __float2bfloat16_rn(v.y - __bfloat162float(h1));
    __nv_bfloat16 l2 = __float2bfloat16_rn(v.z - __bfloat162float(h2));
    __nv_bfloat16 l3 = __float2bfloat16_rn(v.w - __bfloat162float(h3));
    unsigned short s0 = *(unsigned short*)&h0, s1 = *(unsigned short*)&h1;
    unsigned short s2 = *(unsigned short*)&h2, s3 = *(unsigned short*)&h3;
    hi = (ull)s0 | ((ull)s1 << 16) | ((ull)s2 << 32) | ((ull)s3 << 48);
    s0 = *(unsigned short*)&l0; s1 = *(unsigned short*)&l1;
    s2 = *(unsigned short*)&l2; s3 = *(unsigned short*)&l3;
    lo = (ull)s0 | ((ull)s1 << 16) | ((ull)s2 << 32) | ((ull)s3 << 48);
}

// ---------------------------------------------------------------------------
// Kernel 0: pre-split X, Wq, Wk, Wv into bf16 hi/lo (Dekker).
// ---------------------------------------------------------------------------
__global__ __launch_bounds__(256)
void presplit_kernel(const float* __restrict__ X,
                     const float* __restrict__ Wq,
                     const float* __restrict__ Wk,
                     const float* __restrict__ Wv)
{
    const int idx = blockIdx.x * 256 + threadIdx.x;
    if (idx < XCHUNKS) {
        float4 v = ((const float4*)X)[idx];
        ull hi, lo;
        split4(v, hi, lo);
        g_Xhi[idx] = hi;
        g_Xlo[idx] = lo;
    } else {
        const int widx = idx - XCHUNKS;
        if (widx < WCHUNKS) {
            const int kind = widx / (WCHUNKS / 3);
            const int off  = widx % (WCHUNKS / 3);
            const float* W = (kind == 0) ? Wq : (kind == 1) ? Wk : Wv;
            float4 v = ((const float4*)W)[off];
            ull hi, lo;
            split4(v, hi, lo);
            g_Whi[widx] = hi;
            g_Wlo[widx] = lo;
        }
    }
}

// ---------------------------------------------------------------------------
// Kernel A: pure-bf16 x3 WMMA GEMM, K=128 fully smem-resident (R10, proven).
// ---------------------------------------------------------------------------
#define TLD 136
#define TILE_E (128 * TLD)
#define CLD 132
#define GEMM_SMEM (4 * TILE_E * 2)         // 139264 B

__global__ __launch_bounds__(256)
void qkv_gemm_kernel(const float* __restrict__ bq,
                     const float* __restrict__ bk,
                     const float* __restrict__ bv,
                     float* __restrict__ QKV)
{
    extern __shared__ __align__(16) char smem[];
    __nv_bfloat16* Ahi = (__nv_bfloat16*)smem;
    __nv_bfloat16* Alo = Ahi + TILE_E;
    __nv_bfloat16* Bhi = Alo + TILE_E;
    __nv_bfloat16* Blo = Bhi + TILE_E;
    float* Cst = (float*)smem;

    const int bm   = blockIdx.x * 128;
    const int kind = blockIdx.y;
    const int bn   = kind * 128;
    const float* bias = (kind == 0) ? bq : (kind == 1) ? bk : bv;

    const int tid = threadIdx.x;
    const int wid = tid >> 5;
    const int warp_m = wid & 3;
    const int warp_n = wid >> 2;

#pragma unroll
    for (int l = 0; l < 8; l++) {
        const int idx = tid + l * 256;
        const int r = idx >> 4, c = idx & 15;
        const int gsrc = (bm + r) * 16 + c;
        *(uint4*)&Ahi[r * TLD + c * 8] = ((const uint4*)g_Xhi)[gsrc];
        *(uint4*)&Alo[r * TLD + c * 8] = ((const uint4*)g_Xlo)[gsrc];
        const int wsrc = kind * 2048 + r * 16 + c;
        *(uint4*)&Bhi[r * TLD + c * 8] = ((const uint4*)g_Whi)[wsrc];
        *(uint4*)&Blo[r * TLD + c * 8] = ((const uint4*)g_Wlo)[wsrc];
    }
    __syncthreads();

    wmma::fragment<wmma::accumulator, 16, 16, 16, float> acc[2][4];
#pragma unroll
    for (int i = 0; i < 2; i++)
#pragma unroll
        for (int j = 0; j < 4; j++) wmma::fill_fragment(acc[i][j], 0.f);

#pragma unroll
    for (int ks = 0; ks < CIN; ks += 16) {
        wmma::fragment<wmma::matrix_a, 16, 16, 16, __nv_bfloat16, wmma::row_major> ah[2], al[2];
        wmma::fragment<wmma::matrix_b, 16, 16, 16, __nv_bfloat16, wmma::row_major> bh[4], bl[4];
#pragma unroll
        for (int i = 0; i < 2; i++) {
            const int row = warp_m * 32 + i * 16;
            wmma::load_matrix_sync(ah[i], Ahi + row * TLD + ks, TLD);
            wmma::load_matrix_sync(al[i], Alo + row * TLD + ks, TLD);
        }
#pragma unroll
        for (int j = 0; j < 4; j++) {
            const int col = warp_n * 64 + j * 16;
            wmma::load_matrix_sync(bh[j], Bhi + ks * TLD + col, TLD);
            wmma::load_matrix_sync(bl[j], Blo + ks * TLD + col, TLD);
        }
#pragma unroll
        for (int i = 0; i < 2; i++)
#pragma unroll
            for (int j = 0; j < 4; j++) {
                wmma::mma_sync(acc[i][j], ah[i], bh[j], acc[i][j]);
                wmma::mma_sync(acc[i][j], al[i], bh[j], acc[i][j]);
                wmma::mma_sync(acc[i][j], ah[i], bl[j], acc[i][j]);
            }
    }

    __syncthreads();
#pragma unroll
    for (int i = 0; i < 2; i++)
#pragma unroll
        for (int j = 0; j < 4; j++)
            wmma::store_matrix_sync(Cst + (warp_m * 32 + i * 16) * CLD + warp_n * 64 + j * 16,
                                    acc[i][j], CLD, wmma::mem_row_major);
    __syncthreads();

#pragma unroll
    for (int l = 0; l < 16; l++) {
        const int idx = tid + l * 256;
        const int r = idx >> 5, c4 = idx & 31;
        float4 v = *(float4*)&Cst[r * CLD + c4 * 4];
        v.x += bias[c4 * 4 + 0];
        v.y += bias[c4 * 4 + 1];
        v.z += bias[c4 * 4 + 2];
        v.w += bias[c4 * 4 + 3];
        *(float4*)(QKV + (size_t)(bm + r) * NQKV + bn + c4 * 4) = v;
    }
}

// ---------------------------------------------------------------------------
// Kernel B: vertical 1x4 pixel-quad one-pass local attention.
// Tile 16x16, 64 threads: thread (xp, yq) owns pixels (xp, 4*yq + b), b=0..3.
// Union window 10 rows x 7 cols = 70 positions serves 4 pixels
// (17.5 pos/px vs 28 for the pair kernel -> 0.625x LDS traffic).
// Same halo layout (22x22, PSTR=20) and lane-stride pattern as the proven
// pair kernel. OOB halo zero-filled; no-max softmax (scores |s| << 88).
// ---------------------------------------------------------------------------
#define TILE    16
#define HALO    22
#define NHALO   (HALO*HALO)     // 484
#define PSTR    20
#define ATTN_SMEM (2 * NHALO * PSTR * 4)   // 77440 B

__device__ __forceinline__ void attn_step(const ull* q, const ull* kr, const ull* vr,
                                          ull* o, float& sum, float qeval) {
    ull m0, m1;
    MUL2(m0, q[0], kr[0]);
    MUL2(m1, q[1], kr[1]);
    FMA2(m0, q[2], kr[2]);
    FMA2(m1, q[3], kr[3]);
    FMA2(m0, q[4], kr[4]);
    FMA2(m1, q[5], kr[5]);
    FMA2(m0, q[6], kr[6]);
    FMA2(m1, q[7], kr[7]);
    ADD2(m0, m0, m1);
    float lo, hi;
    UNPK2(lo, hi, m0);
    const float e = __expf(lo + hi + qeval);
    sum += e;
    ull ep; PACK2(ep, e, e);
#pragma unroll
    for (int j = 0; j < 8; j++) FMA2(o[j], ep, vr[j]);
}

__global__ __launch_bounds__(64)
void attn_kernel(const float* __restrict__ QKV,
                 const float* __restrict__ emb0,   // [64,7]
                 const float* __restrict__ emb1,   // [64,7]
                 float* __restrict__ out)
{
    extern __shared__ float sbuf[];
    float* bufK = sbuf;
    float* bufV = sbuf + NHALO * PSTR;

    const int tid = threadIdx.x;
    const int xp  = tid & 15;
    const int yq  = tid >> 4;          // 0..3 (4 pixel rows each)
    const int tx0 = (blockIdx.x & 3) * TILE;
    const int ty0 = (blockIdx.x >> 2) * TILE;
    const int b   = blockIdx.y;
    const int h   = blockIdx.z;

    // ---- load K and V halos (zero-filled OOB), 64 threads ----
    {
        const int koff = FILTERS + h * HSIZE;
        const int voff = 2 * FILTERS + h * HSIZE;
        for (int i = tid; i < NHALO * 4; i += 64) {
            const int hp = i >> 2, c4 = i & 3;
            const int hy = hp / HALO, hx = hp % HALO;
            const int sy = ty0 + hy - 3, sx = tx0 + hx - 3;
            float4 kv = make_float4(0.f, 0.f, 0.f, 0.f);
            float4 vv = make_float4(0.f, 0.f, 0.f, 0.f);
            if ((unsigned)sy < HH && (unsigned)sx < WW) {
                const float* base = QKV + (size_t)(((b * HH) + sy) * WW + sx) * NQKV;
                kv = *(const float4*)(base + koff + c4 * 4);
                vv = *(const float4*)(base + voff + c4 * 4);
            }
            *(float4*)&bufK[hp * PSTR + c4 * 4] = kv;
            *(float4*)&bufV[hp * PSTR + c4 * 4] = vv;
        }
    }

    // ---- load 4 q vectors ----
    const int y0   = ty0 + 4 * yq;
    const int pix0 = ((b * HH) + y0) * WW + (tx0 + xp);
    ull q[4][8];
#pragma unroll
    for (int p = 0; p < 4; p++) {
        const ulonglong2* qp =
            (const ulonglong2*)(QKV + (size_t)(pix0 + p * WW) * NQKV + h * HSIZE);
#pragma unroll
        for (int j = 0; j < 4; j++) {
            ulonglong2 t = qp[j];
            q[p][2*j] = t.x; q[p][2*j+1] = t.y;
        }
    }

    // ---- qe tables (per pixel, 7 entries) ----
    const bool use0 = (h < 4);
    float qe[4][7];
    {
        const float* etab = use0 ? (emb0 + h * HSIZE * K0)
                                 : (emb1 + (h * HSIZE - 64) * K1);
#pragma unroll
        for (int p = 0; p < 4; p++) {
            float qf[16];
#pragma unroll
            for (int j = 0; j < 8; j++) UNPK2(qf[2*j], qf[2*j+1], q[p][j]);
#pragma unroll
            for (int r = 0; r < 7; r++) {
                float s = 0.f;
#pragma unroll
                for (int d = 0; d < 16; d++) s += qf[d] * etab[d * 7 + r];
                qe[p][r] = s;
            }
        }
    }

    __syncthreads();

    // ---- one-pass softmax-attention over 10x7 union window ----
    float sum[4] = {0.f, 0.f, 0.f, 0.f};
    ull o[4][8];
#pragma unroll
    for (int p = 0; p < 4; p++)
#pragma unroll
        for (int j = 0; j < 8; j++) o[p][j] = 0ull;

#pragma unroll
    for (int dr = 0; dr < 10; dr++) {
#pragma unroll
        for (int dj = 0; dj < 7; dj++) {
            const int eoff = ((4 * yq + dr) * HALO + (xp + dj)) * PSTR;
            const float* kp = bufK + eoff;
            const float* vp = bufV + eoff;
            ull kr[8], vr[8];
            {
                ulonglong2 t;
                t = *(const ulonglong2*)(kp +  0); kr[0]=t.x; kr[1]=t.y;
                t = *(const ulonglong2*)(kp +  4); kr[2]=t.x; kr[3]=t.y;
                t = *(const ulonglong2*)(kp +  8); kr[4]=t.x; kr[5]=t.y;
                t = *(const ulonglong2*)(kp + 12); kr[6]=t.x; kr[7]=t.y;
                t = *(const ulonglong2*)(vp +  0); vr[0]=t.x; vr[1]=t.y;
                t = *(const ulonglong2*)(vp +  4); vr[2]=t.x; vr[3]=t.y;
                t = *(const ulonglong2*)(vp +  8); vr[4]=t.x; vr[5]=t.y;
                t = *(const ulonglong2*)(vp + 12); vr[6]=t.x; vr[7]=t.y;
            }
            // pixel b active iff 0 <= dr-b <= 6  (compile-time per dr)
            if (dr <= 6)
                attn_step(q[0], kr, vr, o[0], sum[0], use0 ? qe[0][dr]   : qe[0][dj]);
            if (dr >= 1 && dr <= 7)
                attn_step(q[1], kr, vr, o[1], sum[1], use0 ? qe[1][dr-1] : qe[1][dj]);
            if (dr >= 2 && dr <= 8)
                attn_step(q[2], kr, vr, o[2], sum[2], use0 ? qe[2][dr-2] : qe[2][dj]);
            if (dr >= 3)
                attn_step(q[3], kr, vr, o[3], sum[3], use0 ? qe[3][dr-3] : qe[3][dj]);
        }
    }

    // ---- normalize + store 4 pixels ----
#pragma unroll
    for (int p = 0; p < 4; p++) {
        const float inv = 1.f / sum[p];
        float* op = out + (size_t)(pix0 + p * WW) * FILTERS + h * HSIZE;
#pragma unroll
        for (int j = 0; j < 4; j++) {
            float a0, a1, b0, b1;
            UNPK2(a0, a1, o[p][2*j]);
            UNPK2(b0, b1, o[p][2*j+1]);
            *(float4*)(op + j*4) = make_float4(a0*inv, a1*inv, b0*inv, b1*inv);
        }
    }
}

// ---------------------------------------------------------------------------
extern "C" void kernel_launch(void* const* d_in, const int* in_sizes, int n_in,
                              void* d_out, int out_size)
{
    const float* x    = (const float*)d_in[0];
    const float* Wq   = (const float*)d_in[1];
    const float* bq   = (const float*)d_in[2];
    const float* Wk   = (const float*)d_in[3];
    const float* bk   = (const float*)d_in[4];
    const float* Wv   = (const float*)d_in[5];
    const float* bv   = (const float*)d_in[6];
    const float* emb0 = (const float*)d_in[7];
    const float* emb1 = (const float*)d_in[8];
    float* out = (float*)d_out;

    float* qkv = nullptr;
    cudaGetSymbolAddress((void**)&qkv, g_QKV);

    cudaFuncSetAttribute(qkv_gemm_kernel,
                         cudaFuncAttributeMaxDynamicSharedMemorySize, GEMM_SMEM);
    cudaFuncSetAttribute(attn_kernel,
                         cudaFuncAttributeMaxDynamicSharedMemorySize, ATTN_SMEM);

    const int total_chunks = XCHUNKS + WCHUNKS;
    presplit_kernel<<<(total_chunks + 255) / 256, 256>>>(x, Wq, Wk, Wv);

    dim3 gg(NPIX / 128, 3);
    qkv_gemm_kernel<<<gg, 256, GEMM_SMEM>>>(bq, bk, bv, qkv);

    dim3 ga(16, BATCH, HEADS);         // 512 blocks, 64 threads each
    attn_kernel<<<ga, 64, ATTN_SMEM>>>(qkv, emb0, emb1, out);
}

// round 12
// speedup vs baseline: 1.0950x; 1.0950x over previous
#include <cuda_runtime.h>
#include <cuda_bf16.h>
#include <mma.h>
#include <math.h>

using namespace nvcuda;

// Problem constants
#define BATCH   4
#define HH      64
#define WW      64
#define CIN     128
#define FILTERS 128
#define HEADS   8
#define HSIZE   16
#define K0      7
#define K1      7
#define KD      49
#define NPIX    (BATCH*HH*WW)      // 16384
#define NQKV    384                 // q|k|v concat

typedef unsigned long long ull;
typedef unsigned int u32;

// packed f32x2 helpers (sm_100+)
#define FMA2(d, a, b)   asm("fma.rn.f32x2 %0, %1, %2, %0;" : "+l"(d) : "l"(a), "l"(b))
#define MUL2(d, a, b)   asm("mul.rn.f32x2 %0, %1, %2;"     : "=l"(d) : "l"(a), "l"(b))
#define ADD2(d, a, b)   asm("add.rn.f32x2 %0, %1, %2;"     : "=l"(d) : "l"(a), "l"(b))
#define PACK2(d, x, y)  asm("mov.b64 %0, {%1, %2};" : "=l"(d) : "f"(x), "f"(y))
#define UNPK2(lo, hi, s) asm("mov.b64 {%0, %1}, %2;" : "=f"(lo), "=f"(hi) : "l"(s))

__device__ float g_QKV[NPIX * NQKV];

// pre-split bf16 hi/lo storage for W only (4 bf16 per ull)
#define WCHUNKS (3 * CIN * FILTERS / 4)   // 12288
__device__ ull g_Whi[WCHUNKS];
__device__ ull g_Wlo[WCHUNKS];

__device__ __forceinline__ void split4(float4 v, ull& hi, ull& lo) {
    __nv_bfloat16 h0 = __float2bfloat16_rn(v.x);
    __nv_bfloat16 h1 = __float2bfloat16_rn(v.y);
    __nv_bfloat16 h2 = __float2bfloat16_rn(v.z);
    __nv_bfloat16 h3 = __float2bfloat16_rn(v.w);
    __nv_bfloat16 l0 = __float2bfloat16_rn(v.x - __bfloat162float(h0));
    __nv_bfloat16 l1 = __float2bfloat16_rn(v.y - __bfloat162float(h1));
    __nv_bfloat16 l2 = __float2bfloat16_rn(v.z - __bfloat162float(h2));
    __nv_bfloat16 l3 = __float2bfloat16_rn(v.w - __bfloat162float(h3));
    unsigned short s0 = *(unsigned short*)&h0, s1 = *(unsigned short*)&h1;
    unsigned short s2 = *(unsigned short*)&h2, s3 = *(unsigned short*)&h3;
    hi = (ull)s0 | ((ull)s1 << 16) | ((ull)s2 << 32) | ((ull)s3 << 48);
    s0 = *(unsigned short*)&l0; s1 = *(unsigned short*)&l1;
    s2 = *(unsigned short*)&l2; s3 = *(unsigned short*)&l3;
    lo = (ull)s0 | ((ull)s1 << 16) | ((ull)s2 << 32) | ((ull)s3 << 48);
}

// ---------------------------------------------------------------------------
// Kernel 0: pre-split Wq, Wk, Wv into bf16 hi/lo (tiny: 48 blocks).
// ---------------------------------------------------------------------------
__global__ __launch_bounds__(256)
void presplit_kernel(const float* __restrict__ Wq,
                     const float* __restrict__ Wk,
                     const float* __restrict__ Wv)
{
    const int widx = blockIdx.x * 256 + threadIdx.x;
    if (widx < WCHUNKS) {
        const int kind = widx / (WCHUNKS / 3);
        const int off  = widx % (WCHUNKS / 3);
        const float* W = (kind == 0) ? Wq : (kind == 1) ? Wk : Wv;
        float4 v = ((const float4*)W)[off];
        ull hi, lo;
        split4(v, hi, lo);
        g_Whi[widx] = hi;
        g_Wlo[widx] = lo;
    }
}

// ---------------------------------------------------------------------------
// Kernel A: bf16x3 WMMA GEMM, K=128 smem-resident, X split inline at load.
// D = Xhi*Whi + Xlo*Whi + Xhi*Wlo  (fp32 accum, ~1e-5 rel err)
// Block: BM=128 x BN=64, 256 thr (8 warps 4x2, warp 32x32, 2x2 frags).
// smem ~107 KB -> 2 blocks/SM: load phase of one block hides under the
// other's HMMA. grid (128, 6): y = kind*2 + half.
// ---------------------------------------------------------------------------
#define TLD 136      // A row stride (bf16 elems), odd-16B -> LDSM clean
#define BLD2 72      // B row stride
#define CLD 68
#define A_E (128 * TLD)
#define B_E (128 * BLD2)
#define GEMM_SMEM ((2 * A_E + 2 * B_E) * 2)   // 106496 B

__global__ __launch_bounds__(256)
void qkv_gemm_kernel(const float* __restrict__ X,
                     const float* __restrict__ bq,
                     const float* __restrict__ bk,
                     const float* __restrict__ bv,
                     float* __restrict__ QKV)
{
    extern __shared__ __align__(16) char smem[];
    __nv_bfloat16* Ahi = (__nv_bfloat16*)smem;
    __nv_bfloat16* Alo = Ahi + A_E;
    __nv_bfloat16* Bhi = Alo + A_E;
    __nv_bfloat16* Blo = Bhi + B_E;
    float* Cst = (float*)smem;                 // epilogue staging (34.8 KB)

    const int bm   = blockIdx.x * 128;
    const int kind = blockIdx.y >> 1;          // 0/1/2 -> q/k/v
    const int half = blockIdx.y & 1;           // 0/1 -> cols 0-63 / 64-127
    const float* bias = (kind == 0) ? bq : (kind == 1) ? bk : bv;

    const int tid = threadIdx.x;
    const int wid = tid >> 5;
    const int warp_m = wid & 3;                // 4 row-warps x 32 rows
    const int warp_n = wid >> 2;               // 2 col-warps x 32 cols

    // ---- load + split A tile: 128 x 128 fp32 -> bf16 hi/lo ----
#pragma unroll
    for (int l = 0; l < 8; l++) {
        const int idx = tid + l * 256;         // 0..2047 groups of 8 elems
        const int r = idx >> 4, c = idx & 15;
        const float* src = X + (size_t)(bm + r) * CIN + c * 8;
        float4 v0 = *(const float4*)(src);
        float4 v1 = *(const float4*)(src + 4);
        ull h0, l0, h1, l1;
        split4(v0, h0, l0);
        split4(v1, h1, l1);
        ull* ah = (ull*)&Ahi[r * TLD + c * 8];
        ull* al = (ull*)&Alo[r * TLD + c * 8];
        ah[0] = h0; ah[1] = h1;
        al[0] = l0; al[1] = l1;
    }
    // ---- load B tiles (pre-split): 128 k-rows x 64 cols ----
#pragma unroll
    for (int l = 0; l < 4; l++) {
        const int idx = tid + l * 256;         // 0..1023
        const int r = idx >> 3, c = idx & 7;   // c: uint4 (8 elems) column
        const int wsrc = kind * 2048 + r * 16 + half * 8 + c;
        *(uint4*)&Bhi[r * BLD2 + c * 8] = ((const uint4*)g_Whi)[wsrc];
        *(uint4*)&Blo[r * BLD2 + c * 8] = ((const uint4*)g_Wlo)[wsrc];
    }
    __syncthreads();

    wmma::fragment<wmma::accumulator, 16, 16, 16, float> acc[2][2];
#pragma unroll
    for (int i = 0; i < 2; i++)
#pragma unroll
        for (int j = 0; j < 2; j++) wmma::fill_fragment(acc[i][j], 0.f);

#pragma unroll
    for (int ks = 0; ks < CIN; ks += 16) {
        wmma::fragment<wmma::matrix_a, 16, 16, 16, __nv_bfloat16, wmma::row_major> ah[2], al[2];
        wmma::fragment<wmma::matrix_b, 16, 16, 16, __nv_bfloat16, wmma::row_major> bh[2], bl[2];
#pragma unroll
        for (int i = 0; i < 2; i++) {
            const int row = warp_m * 32 + i * 16;
            wmma::load_matrix_sync(ah[i], Ahi + row * TLD + ks, TLD);
            wmma::load_matrix_sync(al[i], Alo + row * TLD + ks, TLD);
        }
#pragma unroll
        for (int j = 0; j < 2; j++) {
            const int col = warp_n * 32 + j * 16;
            wmma::load_matrix_sync(bh[j], Bhi + ks * BLD2 + col, BLD2);
            wmma::load_matrix_sync(bl[j], Blo + ks * BLD2 + col, BLD2);
        }
#pragma unroll
        for (int i = 0; i < 2; i++)
#pragma unroll
            for (int j = 0; j < 2; j++) {
                wmma::mma_sync(acc[i][j], ah[i], bh[j], acc[i][j]);
                wmma::mma_sync(acc[i][j], al[i], bh[j], acc[i][j]);
                wmma::mma_sync(acc[i][j], ah[i], bl[j], acc[i][j]);
            }
    }

    // ---- epilogue: stage via smem, add bias, store ----
    __syncthreads();
#pragma unroll
    for (int i = 0; i < 2; i++)
#pragma unroll
        for (int j = 0; j < 2; j++)
            wmma::store_matrix_sync(Cst + (warp_m * 32 + i * 16) * CLD + warp_n * 32 + j * 16,
                                    acc[i][j], CLD, wmma::mem_row_major);
    __syncthreads();

    const int ncol0 = half * 64;               // bias/col base within kind
#pragma unroll
    for (int l = 0; l < 8; l++) {              // 128 rows x 16 f4 (64 cols)
        const int idx = tid + l * 256;
        const int r = idx >> 4, c4 = idx & 15;
        float4 v = *(float4*)&Cst[r * CLD + c4 * 4];
        v.x += bias[ncol0 + c4 * 4 + 0];
        v.y += bias[ncol0 + c4 * 4 + 1];
        v.z += bias[ncol0 + c4 * 4 + 2];
        v.w += bias[ncol0 + c4 * 4 + 3];
        *(float4*)(QKV + (size_t)(bm + r) * NQKV + kind * 128 + ncol0 + c4 * 4) = v;
    }
}

// ---------------------------------------------------------------------------
// Kernel B: pixel-pair one-pass local attention (R10 proven config, verbatim).
// ---------------------------------------------------------------------------
#define TILE    16
#define HALO    22
#define NHALO   (HALO*HALO)     // 484
#define PSTR    20
#define ATTN_SMEM (2 * NHALO * PSTR * 4)   // 77440 B

__global__ __launch_bounds__(128)
void attn_kernel(const float* __restrict__ QKV,
                 const float* __restrict__ emb0,   // [64,7]
                 const float* __restrict__ emb1,   // [64,7]
                 float* __restrict__ out)
{
    extern __shared__ float sbuf[];
    float* bufK = sbuf;
    float* bufV = sbuf + NHALO * PSTR;

    const int tid = threadIdx.x;
    const int px  = tid & 15;
    const int yp  = tid >> 4;          // 0..7
    const int tx0 = (blockIdx.x & 3) * TILE;
    const int ty0 = (blockIdx.x >> 2) * TILE;
    const int b   = blockIdx.y;
    const int h   = blockIdx.z;

    {
        const int koff = FILTERS + h * HSIZE;
        const int voff = 2 * FILTERS + h * HSIZE;
#pragma unroll
        for (int i = tid; i < NHALO * 4; i += 128) {
            const int hp = i >> 2, c4 = i & 3;
            const int hy = hp / HALO, hx = hp % HALO;
            const int sy = ty0 + hy - 3, sx = tx0 + hx - 3;
            float4 kv = make_float4(0.f, 0.f, 0.f, 0.f);
            float4 vv = make_float4(0.f, 0.f, 0.f, 0.f);
            if ((unsigned)sy < HH && (unsigned)sx < WW) {
                const float* base = QKV + (size_t)(((b * HH) + sy) * WW + sx) * NQKV;
                kv = *(const float4*)(base + koff + c4 * 4);
                vv = *(const float4*)(base + voff + c4 * 4);
            }
            *(float4*)&bufK[hp * PSTR + c4 * 4] = kv;
            *(float4*)&bufV[hp * PSTR + c4 * 4] = vv;
        }
    }

    const int y0   = ty0 + 2 * yp;
    const int pix0 = ((b * HH) + y0) * WW + (tx0 + px);
    const int pix1 = pix0 + WW;

    ull q0[8], q1[8];
    {
        const ulonglong2* qp0 = (const ulonglong2*)(QKV + (size_t)pix0 * NQKV + h * HSIZE);
        const ulonglong2* qp1 = (const ulonglong2*)(QKV + (size_t)pix1 * NQKV + h * HSIZE);
#pragma unroll
        for (int j = 0; j < 4; j++) {
            ulonglong2 t0 = qp0[j];
            ulonglong2 t1 = qp1[j];
            q0[2*j] = t0.x; q0[2*j+1] = t0.y;
            q1[2*j] = t1.x; q1[2*j+1] = t1.y;
        }
    }

    const bool use0 = (h < 4);
    float qe0[7], qe1[7];
    {
        const float* etab = use0 ? (emb0 + h * HSIZE * K0)
                                 : (emb1 + (h * HSIZE - 64) * K1);
        float qf0[16], qf1[16];
#pragma unroll
        for (int j = 0; j < 8; j++) {
            UNPK2(qf0[2*j], qf0[2*j+1], q0[j]);
            UNPK2(qf1[2*j], qf1[2*j+1], q1[j]);
        }
#pragma unroll
        for (int r = 0; r < 7; r++) {
            float s0 = 0.f, s1 = 0.f;
#pragma unroll
            for (int d = 0; d < 16; d++) {
                const float e = etab[d * 7 + r];
                s0 += qf0[d] * e;
                s1 += qf1[d] * e;
            }
            qe0[r] = s0;
            qe1[r] = s1;
        }
    }

    __syncthreads();

    float sum0 = 0.f, sum1 = 0.f;
    ull o0[8], o1[8];
#pragma unroll
    for (int j = 0; j < 8; j++) { o0[j] = 0ull; o1[j] = 0ull; }

#pragma unroll
    for (int dr = 0; dr < 8; dr++) {
#pragma unroll
        for (int dj = 0; dj < 7; dj++) {
            const int eoff = ((2*yp + dr) * HALO + (px + dj)) * PSTR;
            const float* kp = bufK + eoff;
            const float* vp = bufV + eoff;
            ull kr[8], vr[8];
            {
                ulonglong2 t;
                t = *(const ulonglong2*)(kp +  0); kr[0]=t.x; kr[1]=t.y;
                t = *(const ulonglong2*)(kp +  4); kr[2]=t.x; kr[3]=t.y;
                t = *(const ulonglong2*)(kp +  8); kr[4]=t.x; kr[5]=t.y;
                t = *(const ulonglong2*)(kp + 12); kr[6]=t.x; kr[7]=t.y;
                t = *(const ulonglong2*)(vp +  0); vr[0]=t.x; vr[1]=t.y;
                t = *(const ulonglong2*)(vp +  4); vr[2]=t.x; vr[3]=t.y;
                t = *(const ulonglong2*)(vp +  8); vr[4]=t.x; vr[5]=t.y;
                t = *(const ulonglong2*)(vp + 12); vr[6]=t.x; vr[7]=t.y;
            }

            if (dr < 7) {
                ull m0, m1;
                MUL2(m0, q0[0], kr[0]);
                MUL2(m1, q0[1], kr[1]);
                FMA2(m0, q0[2], kr[2]);
                FMA2(m1, q0[3], kr[3]);
                FMA2(m0, q0[4], kr[4]);
                FMA2(m1, q0[5], kr[5]);
                FMA2(m0, q0[6], kr[6]);
                FMA2(m1, q0[7], kr[7]);
                ADD2(m0, m0, m1);
                float lo, hi;
                UNPK2(lo, hi, m0);
                const float s = lo + hi + (use0 ? qe0[dr] : qe0[dj]);
                const float e = __expf(s);
                sum0 += e;
                ull ep; PACK2(ep, e, e);
#pragma unroll
                for (int j = 0; j < 8; j++) FMA2(o0[j], ep, vr[j]);
            }
            if (dr > 0) {
                ull m0, m1;
                MUL2(m0, q1[0], kr[0]);
                MUL2(m1, q1[1], kr[1]);
                FMA2(m0, q1[2], kr[2]);
                FMA2(m1, q1[3], kr[3]);
                FMA2(m0, q1[4], kr[4]);
                FMA2(m1, q1[5], kr[5]);
                FMA2(m0, q1[6], kr[6]);
                FMA2(m1, q1[7], kr[7]);
                ADD2(m0, m0, m1);
                float lo, hi;
                UNPK2(lo, hi, m0);
                const float s = lo + hi + (use0 ? qe1[dr-1] : qe1[dj]);
                const float e = __expf(s);
                sum1 += e;
                ull ep; PACK2(ep, e, e);
#pragma unroll
                for (int j = 0; j < 8; j++) FMA2(o1[j], ep, vr[j]);
            }
        }
    }

    const float inv0 = 1.f / sum0;
    const float inv1 = 1.f / sum1;
    float* op0 = out + (size_t)pix0 * FILTERS + h * HSIZE;
    float* op1 = out + (size_t)pix1 * FILTERS + h * HSIZE;
#pragma unroll
    for (int j = 0; j < 4; j++) {
        float a0, a1, b0, b1;
        UNPK2(a0, a1, o0[2*j]);
        UNPK2(b0, b1, o0[2*j+1]);
        float4 r0 = make_float4(a0*inv0, a1*inv0, b0*inv0, b1*inv0);
        *(float4*)(op0 + j*4) = r0;
        UNPK2(a0, a1, o1[2*j]);
        UNPK2(b0, b1, o1[2*j+1]);
        float4 r1 = make_float4(a0*inv1, a1*inv1, b0*inv1, b1*inv1);
        *(float4*)(op1 + j*4) = r1;
    }
}

// ---------------------------------------------------------------------------
extern "C" void kernel_launch(void* const* d_in, const int* in_sizes, int n_in,
                              void* d_out, int out_size)
{
    const float* x    = (const float*)d_in[0];
    const float* Wq   = (const float*)d_in[1];
    const float* bq   = (const float*)d_in[2];
    const float* Wk   = (const float*)d_in[3];
    const float* bk   = (const float*)d_in[4];
    const float* Wv   = (const float*)d_in[5];
    const float* bv   = (const float*)d_in[6];
    const float* emb0 = (const float*)d_in[7];
    const float* emb1 = (const float*)d_in[8];
    float* out = (float*)d_out;

    float* qkv = nullptr;
    cudaGetSymbolAddress((void**)&qkv, g_QKV);

    cudaFuncSetAttribute(qkv_gemm_kernel,
                         cudaFuncAttributeMaxDynamicSharedMemorySize, GEMM_SMEM);
    cudaFuncSetAttribute(attn_kernel,
                         cudaFuncAttributeMaxDynamicSharedMemorySize, ATTN_SMEM);

    presplit_kernel<<<(WCHUNKS + 255) / 256, 256>>>(Wq, Wk, Wv);

    dim3 gg(NPIX / 128, 6);
    qkv_gemm_kernel<<<gg, 256, GEMM_SMEM>>>(x, bq, bk, bv, qkv);

    dim3 ga(16, BATCH, HEADS);         // 512 blocks
    attn_kernel<<<ga, 128, ATTN_SMEM>>>(qkv, emb0, emb1, out);
}

// round 13
// speedup vs baseline: 1.1325x; 1.0342x over previous
#include <cuda_runtime.h>
#include <cuda_bf16.h>
#include <mma.h>
#include <math.h>

using namespace nvcuda;

// Problem constants
#define BATCH   4
#define HH      64
#define WW      64
#define CIN     128
#define FILTERS 128
#define HEADS   8
#define HSIZE   16
#define K0      7
#define K1      7
#define KD      49
#define NPIX    (BATCH*HH*WW)      // 16384
#define NQKV    384                 // q|k|v concat

typedef unsigned long long ull;
typedef unsigned int u32;

// packed f32x2 helpers (sm_100+)
#define FMA2(d, a, b)   asm("fma.rn.f32x2 %0, %1, %2, %0;" : "+l"(d) : "l"(a), "l"(b))
#define MUL2(d, a, b)   asm("mul.rn.f32x2 %0, %1, %2;"     : "=l"(d) : "l"(a), "l"(b))
#define ADD2(d, a, b)   asm("add.rn.f32x2 %0, %1, %2;"     : "=l"(d) : "l"(a), "l"(b))
#define PACK2(d, x, y)  asm("mov.b64 %0, {%1, %2};" : "=l"(d) : "f"(x), "f"(y))
#define UNPK2(lo, hi, s) asm("mov.b64 {%0, %1}, %2;" : "=f"(lo), "=f"(hi) : "l"(s))

__device__ float g_QKV[NPIX * NQKV];

__device__ __forceinline__ void split4(float4 v, ull& hi, ull& lo) {
    __nv_bfloat16 h0 = __float2bfloat16_rn(v.x);
    __nv_bfloat16 h1 = __float2bfloat16_rn(v.y);
    __nv_bfloat16 h2 = __float2bfloat16_rn(v.z);
    __nv_bfloat16 h3 = __float2bfloat16_rn(v.w);
    __nv_bfloat16 l0 = __float2bfloat16_rn(v.x - __bfloat162float(h0));
    __nv_bfloat16 l1 = __float2bfloat16_rn(v.y - __bfloat162float(h1));
    __nv_bfloat16 l2 = __float2bfloat16_rn(v.z - __bfloat162float(h2));
    __nv_bfloat16 l3 = __float2bfloat16_rn(v.w - __bfloat162float(h3));
    unsigned short s0 = *(unsigned short*)&h0, s1 = *(unsigned short*)&h1;
    unsigned short s2 = *(unsigned short*)&h2, s3 = *(unsigned short*)&h3;
    hi = (ull)s0 | ((ull)s1 << 16) | ((ull)s2 << 32) | ((ull)s3 << 48);
    s0 = *(unsigned short*)&l0; s1 = *(unsigned short*)&l1;
    s2 = *(unsigned short*)&l2; s3 = *(unsigned short*)&l3;
    lo = (ull)s0 | ((ull)s1 << 16) | ((ull)s2 << 32) | ((ull)s3 << 48);
}

// ---------------------------------------------------------------------------
// Kernel A: bf16x3 WMMA GEMM (R10 shape), X AND W split inline at load.
// D = Xhi*Whi + Xlo*Whi + Xhi*Wlo  (fp32 accum, ~1e-5 rel err)
// Block: BM=128 x BN=128 (one kind), 256 thr (8 warps 4x2, warp 32x64).
// Tiles 128x128 bf16, 136-elem row stride (odd-16B): conflict-free LDSM.
// ---------------------------------------------------------------------------
#define TLD 136
#define TILE_E (128 * TLD)
#define CLD 132
#define GEMM_SMEM (4 * TILE_E * 2)         // 139264 B

__global__ __launch_bounds__(256)
void qkv_gemm_kernel(const float* __restrict__ X,
                     const float* __restrict__ Wq, const float* __restrict__ bq,
                     const float* __restrict__ Wk, const float* __restrict__ bk,
                     const float* __restrict__ Wv, const float* __restrict__ bv,
                     float* __restrict__ QKV)
{
    extern __shared__ __align__(16) char smem[];
    __nv_bfloat16* Ahi = (__nv_bfloat16*)smem;
    __nv_bfloat16* Alo = Ahi + TILE_E;
    __nv_bfloat16* Bhi = Alo + TILE_E;
    __nv_bfloat16* Blo = Bhi + TILE_E;
    float* Cst = (float*)smem;

    const int bm   = blockIdx.x * 128;
    const int kind = blockIdx.y;           // 0/1/2 -> q/k/v
    const int bn   = kind * 128;
    const float* W;  const float* bias;
    if (kind == 0)      { W = Wq; bias = bq; }
    else if (kind == 1) { W = Wk; bias = bk; }
    else                { W = Wv; bias = bv; }

    const int tid = threadIdx.x;
    const int wid = tid >> 5;
    const int warp_m = wid & 3;
    const int warp_n = wid >> 2;

    // ---- load + split A (X rows) and B (W rows): 128 x 128 fp32 each ----
#pragma unroll
    for (int l = 0; l < 8; l++) {
        const int idx = tid + l * 256;     // 0..2047, groups of 8 elems
        const int r = idx >> 4, c = idx & 15;
        {
            const float* src = X + (size_t)(bm + r) * CIN + c * 8;
            float4 v0 = *(const float4*)(src);
            float4 v1 = *(const float4*)(src + 4);
            ull h0, l0w, h1, l1w;
            split4(v0, h0, l0w);
            split4(v1, h1, l1w);
            ull* ah = (ull*)&Ahi[r * TLD + c * 8];
            ull* al = (ull*)&Alo[r * TLD + c * 8];
            ah[0] = h0; ah[1] = h1;
            al[0] = l0w; al[1] = l1w;
        }
        {
            const float* src = W + (size_t)r * FILTERS + c * 8;
            float4 v0 = *(const float4*)(src);
            float4 v1 = *(const float4*)(src + 4);
            ull h0, l0w, h1, l1w;
            split4(v0, h0, l0w);
            split4(v1, h1, l1w);
            ull* bh = (ull*)&Bhi[r * TLD + c * 8];
            ull* bl = (ull*)&Blo[r * TLD + c * 8];
            bh[0] = h0; bh[1] = h1;
            bl[0] = l0w; bl[1] = l1w;
        }
    }
    __syncthreads();

    wmma::fragment<wmma::accumulator, 16, 16, 16, float> acc[2][4];
#pragma unroll
    for (int i = 0; i < 2; i++)
#pragma unroll
        for (int j = 0; j < 4; j++) wmma::fill_fragment(acc[i][j], 0.f);

#pragma unroll
    for (int ks = 0; ks < CIN; ks += 16) {
        wmma::fragment<wmma::matrix_a, 16, 16, 16, __nv_bfloat16, wmma::row_major> ah[2], al[2];
        wmma::fragment<wmma::matrix_b, 16, 16, 16, __nv_bfloat16, wmma::row_major> bh[4], bl[4];
#pragma unroll
        for (int i = 0; i < 2; i++) {
            const int row = warp_m * 32 + i * 16;
            wmma::load_matrix_sync(ah[i], Ahi + row * TLD + ks, TLD);
            wmma::load_matrix_sync(al[i], Alo + row * TLD + ks, TLD);
        }
#pragma unroll
        for (int j = 0; j < 4; j++) {
            const int col = warp_n * 64 + j * 16;
            wmma::load_matrix_sync(bh[j], Bhi + ks * TLD + col, TLD);
            wmma::load_matrix_sync(bl[j], Blo + ks * TLD + col, TLD);
        }
#pragma unroll
        for (int i = 0; i < 2; i++)
#pragma unroll
            for (int j = 0; j < 4; j++) {
                wmma::mma_sync(acc[i][j], ah[i], bh[j], acc[i][j]);
                wmma::mma_sync(acc[i][j], al[i], bh[j], acc[i][j]);
                wmma::mma_sync(acc[i][j], ah[i], bl[j], acc[i][j]);
            }
    }

    __syncthreads();
#pragma unroll
    for (int i = 0; i < 2; i++)
#pragma unroll
        for (int j = 0; j < 4; j++)
            wmma::store_matrix_sync(Cst + (warp_m * 32 + i * 16) * CLD + warp_n * 64 + j * 16,
                                    acc[i][j], CLD, wmma::mem_row_major);
    __syncthreads();

#pragma unroll
    for (int l = 0; l < 16; l++) {
        const int idx = tid + l * 256;
        const int r = idx >> 5, c4 = idx & 31;
        float4 v = *(float4*)&Cst[r * CLD + c4 * 4];
        v.x += bias[c4 * 4 + 0];
        v.y += bias[c4 * 4 + 1];
        v.z += bias[c4 * 4 + 2];
        v.w += bias[c4 * 4 + 3];
        *(float4*)(QKV + (size_t)(bm + r) * NQKV + bn + c4 * 4) = v;
    }
}

// ---------------------------------------------------------------------------
// Kernel B: pixel-pair one-pass local attention (R10 proven config, verbatim).
// ---------------------------------------------------------------------------
#define TILE    16
#define HALO    22
#define NHALO   (HALO*HALO)     // 484
#define PSTR    20
#define ATTN_SMEM (2 * NHALO * PSTR * 4)   // 77440 B

__global__ __launch_bounds__(128)
void attn_kernel(const float* __restrict__ QKV,
                 const float* __restrict__ emb0,   // [64,7]
                 const float* __restrict__ emb1,   // [64,7]
                 float* __restrict__ out)
{
    extern __shared__ float sbuf[];
    float* bufK = sbuf;
    float* bufV = sbuf + NHALO * PSTR;

    const int tid = threadIdx.x;
    const int px  = tid & 15;
    const int yp  = tid >> 4;          // 0..7
    const int tx0 = (blockIdx.x & 3) * TILE;
    const int ty0 = (blockIdx.x >> 2) * TILE;
    const int b   = blockIdx.y;
    const int h   = blockIdx.z;

    {
        const int koff = FILTERS + h * HSIZE;
        const int voff = 2 * FILTERS + h * HSIZE;
#pragma unroll
        for (int i = tid; i < NHALO * 4; i += 128) {
            const int hp = i >> 2, c4 = i & 3;
            const int hy = hp / HALO, hx = hp % HALO;
            const int sy = ty0 + hy - 3, sx = tx0 + hx - 3;
            float4 kv = make_float4(0.f, 0.f, 0.f, 0.f);
            float4 vv = make_float4(0.f, 0.f, 0.f, 0.f);
            if ((unsigned)sy < HH && (unsigned)sx < WW) {
                const float* base = QKV + (size_t)(((b * HH) + sy) * WW + sx) * NQKV;
                kv = *(const float4*)(base + koff + c4 * 4);
                vv = *(const float4*)(base + voff + c4 * 4);
            }
            *(float4*)&bufK[hp * PSTR + c4 * 4] = kv;
            *(float4*)&bufV[hp * PSTR + c4 * 4] = vv;
        }
    }

    const int y0   = ty0 + 2 * yp;
    const int pix0 = ((b * HH) + y0) * WW + (tx0 + px);
    const int pix1 = pix0 + WW;

    ull q0[8], q1[8];
    {
        const ulonglong2* qp0 = (const ulonglong2*)(QKV + (size_t)pix0 * NQKV + h * HSIZE);
        const ulonglong2* qp1 = (const ulonglong2*)(QKV + (size_t)pix1 * NQKV + h * HSIZE);
#pragma unroll
        for (int j = 0; j < 4; j++) {
            ulonglong2 t0 = qp0[j];
            ulonglong2 t1 = qp1[j];
            q0[2*j] = t0.x; q0[2*j+1] = t0.y;
            q1[2*j] = t1.x; q1[2*j+1] = t1.y;
        }
    }

    const bool use0 = (h < 4);
    float qe0[7], qe1[7];
    {
        const float* etab = use0 ? (emb0 + h * HSIZE * K0)
                                 : (emb1 + (h * HSIZE - 64) * K1);
        float qf0[16], qf1[16];
#pragma unroll
        for (int j = 0; j < 8; j++) {
            UNPK2(qf0[2*j], qf0[2*j+1], q0[j]);
            UNPK2(qf1[2*j], qf1[2*j+1], q1[j]);
        }
#pragma unroll
        for (int r = 0; r < 7; r++) {
            float s0 = 0.f, s1 = 0.f;
#pragma unroll
            for (int d = 0; d < 16; d++) {
                const float e = etab[d * 7 + r];
                s0 += qf0[d] * e;
                s1 += qf1[d] * e;
            }
            qe0[r] = s0;
            qe1[r] = s1;
        }
    }

    __syncthreads();

    float sum0 = 0.f, sum1 = 0.f;
    ull o0[8], o1[8];
#pragma unroll
    for (int j = 0; j < 8; j++) { o0[j] = 0ull; o1[j] = 0ull; }

#pragma unroll
    for (int dr = 0; dr < 8; dr++) {
#pragma unroll
        for (int dj = 0; dj < 7; dj++) {
            const int eoff = ((2*yp + dr) * HALO + (px + dj)) * PSTR;
            const float* kp = bufK + eoff;
            const float* vp = bufV + eoff;
            ull kr[8], vr[8];
            {
                ulonglong2 t;
                t = *(const ulonglong2*)(kp +  0); kr[0]=t.x; kr[1]=t.y;
                t = *(const ulonglong2*)(kp +  4); kr[2]=t.x; kr[3]=t.y;
                t = *(const ulonglong2*)(kp +  8); kr[4]=t.x; kr[5]=t.y;
                t = *(const ulonglong2*)(kp + 12); kr[6]=t.x; kr[7]=t.y;
                t = *(const ulonglong2*)(vp +  0); vr[0]=t.x; vr[1]=t.y;
                t = *(const ulonglong2*)(vp +  4); vr[2]=t.x; vr[3]=t.y;
                t = *(const ulonglong2*)(vp +  8); vr[4]=t.x; vr[5]=t.y;
                t = *(const ulonglong2*)(vp + 12); vr[6]=t.x; vr[7]=t.y;
            }

            if (dr < 7) {
                ull m0, m1;
                MUL2(m0, q0[0], kr[0]);
                MUL2(m1, q0[1], kr[1]);
                FMA2(m0, q0[2], kr[2]);
                FMA2(m1, q0[3], kr[3]);
                FMA2(m0, q0[4], kr[4]);
                FMA2(m1, q0[5], kr[5]);
                FMA2(m0, q0[6], kr[6]);
                FMA2(m1, q0[7], kr[7]);
                ADD2(m0, m0, m1);
                float lo, hi;
                UNPK2(lo, hi, m0);
                const float s = lo + hi + (use0 ? qe0[dr] : qe0[dj]);
                const float e = __expf(s);
                sum0 += e;
                ull ep; PACK2(ep, e, e);
#pragma unroll
                for (int j = 0; j < 8; j++) FMA2(o0[j], ep, vr[j]);
            }
            if (dr > 0) {
                ull m0, m1;
                MUL2(m0, q1[0], kr[0]);
                MUL2(m1, q1[1], kr[1]);
                FMA2(m0, q1[2], kr[2]);
                FMA2(m1, q1[3], kr[3]);
                FMA2(m0, q1[4], kr[4]);
                FMA2(m1, q1[5], kr[5]);
                FMA2(m0, q1[6], kr[6]);
                FMA2(m1, q1[7], kr[7]);
                ADD2(m0, m0, m1);
                float lo, hi;
                UNPK2(lo, hi, m0);
                const float s = lo + hi + (use0 ? qe1[dr-1] : qe1[dj]);
                const float e = __expf(s);
                sum1 += e;
                ull ep; PACK2(ep, e, e);
#pragma unroll
                for (int j = 0; j < 8; j++) FMA2(o1[j], ep, vr[j]);
            }
        }
    }

    const float inv0 = 1.f / sum0;
    const float inv1 = 1.f / sum1;
    float* op0 = out + (size_t)pix0 * FILTERS + h * HSIZE;
    float* op1 = out + (size_t)pix1 * FILTERS + h * HSIZE;
#pragma unroll
    for (int j = 0; j < 4; j++) {
        float a0, a1, b0, b1;
        UNPK2(a0, a1, o0[2*j]);
        UNPK2(b0, b1, o0[2*j+1]);
        float4 r0 = make_float4(a0*inv0, a1*inv0, b0*inv0, b1*inv0);
        *(float4*)(op0 + j*4) = r0;
        UNPK2(a0, a1, o1[2*j]);
        UNPK2(b0, b1, o1[2*j+1]);
        float4 r1 = make_float4(a0*inv1, a1*inv1, b0*inv1, b1*inv1);
        *(float4*)(op1 + j*4) = r1;
    }
}

// ---------------------------------------------------------------------------
extern "C" void kernel_launch(void* const* d_in, const int* in_sizes, int n_in,
                              void* d_out, int out_size)
{
    const float* x    = (const float*)d_in[0];
    const float* Wq   = (const float*)d_in[1];
    const float* bq   = (const float*)d_in[2];
    const float* Wk   = (const float*)d_in[3];
    const float* bk   = (const float*)d_in[4];
    const float* Wv   = (const float*)d_in[5];
    const float* bv   = (const float*)d_in[6];
    const float* emb0 = (const float*)d_in[7];
    const float* emb1 = (const float*)d_in[8];
    float* out = (float*)d_out;

    float* qkv = nullptr;
    cudaGetSymbolAddress((void**)&qkv, g_QKV);

    cudaFuncSetAttribute(qkv_gemm_kernel,
                         cudaFuncAttributeMaxDynamicSharedMemorySize, GEMM_SMEM);
    cudaFuncSetAttribute(attn_kernel,
                         cudaFuncAttributeMaxDynamicSharedMemorySize, ATTN_SMEM);

    dim3 gg(NPIX / 128, 3);
    qkv_gemm_kernel<<<gg, 256, GEMM_SMEM>>>(x, Wq, bq, Wk, bk, Wv, bv, qkv);

    dim3 ga(16, BATCH, HEADS);         // 512 blocks
    attn_kernel<<<ga, 128, ATTN_SMEM>>>(qkv, emb0, emb1, out);
}